// round 5
// baseline (speedup 1.0000x reference)
#include <cuda_runtime.h>
#include <math_constants.h>

#define NN 50000
#define NE 600000
#define D 128

typedef unsigned long long ull;

// ---------------- device scratch (no allocs allowed) ----------------
__device__ int   g_deg[NN];
__device__ int   g_rowptr[NN + 1];
__device__ int   g_cursor[NN];
__device__ int   g_csr[NE];
__device__ float g_agg[(size_t)NN * D];
__device__ float g_h[(size_t)NN * D];

// ---------------- f32x2 helpers (Blackwell packed fp32 pipe) ----------------
__device__ __forceinline__ void ffma2(ull& d, ull a, ull b) {
    asm("fma.rn.f32x2 %0, %1, %2, %0;" : "+l"(d) : "l"(a), "l"(b));
}
__device__ __forceinline__ ull pack2(float x, float y) {
    ull r; asm("mov.b64 %0, {%1, %2};" : "=l"(r) : "f"(x), "f"(y)); return r;
}
__device__ __forceinline__ float2 unpack2(ull v) {
    float2 r; asm("mov.b64 {%0, %1}, %2;" : "=f"(r.x), "=f"(r.y) : "l"(v)); return r;
}

// ---------------- CSR construction ----------------
__global__ void k_zero_deg() {
    int i = blockIdx.x * blockDim.x + threadIdx.x;
    if (i < NN) g_deg[i] = 0;
}

__global__ void k_count(const int* __restrict__ dst) {
    int e = blockIdx.x * blockDim.x + threadIdx.x;
    if (e < NE) atomicAdd(&g_deg[dst[e]], 1);
}

// single-block exclusive scan of g_deg -> g_rowptr (+ copy to g_cursor)
__global__ void k_scan() {
    __shared__ int sm[1024];
    const int t = threadIdx.x;
    const int C = (NN + 1023) / 1024;
    int start = t * C;
    int end = start + C; if (end > NN) end = NN;
    if (start > NN) start = NN;

    int s = 0;
    for (int i = start; i < end; i++) s += g_deg[i];
    sm[t] = s;
    __syncthreads();
    for (int off = 1; off < 1024; off <<= 1) {
        int v = 0;
        if (t >= off) v = sm[t - off];
        __syncthreads();
        if (t >= off) sm[t] += v;
        __syncthreads();
    }
    int run = sm[t] - s;  // exclusive base for this chunk
    for (int i = start; i < end; i++) {
        g_rowptr[i] = run;
        g_cursor[i] = run;
        run += g_deg[i];
    }
    if (t == 1023) g_rowptr[NN] = sm[1023];
}

__global__ void k_fill(const int* __restrict__ src, const int* __restrict__ dst) {
    int e = blockIdx.x * blockDim.x + threadIdx.x;
    if (e < NE) {
        int d = dst[e];
        int p = atomicAdd(&g_cursor[d], 1);
        g_csr[p] = src[e];
    }
}

// ---------------- aggregation: warp-per-node gather-max ----------------
__device__ __forceinline__ float4 f4max(float4 a, float4 b) {
    a.x = fmaxf(a.x, b.x); a.y = fmaxf(a.y, b.y);
    a.z = fmaxf(a.z, b.z); a.w = fmaxf(a.w, b.w);
    return a;
}

__global__ void k_agg(const float* __restrict__ xin) {
    int gw = (blockIdx.x * blockDim.x + threadIdx.x) >> 5;
    int lane = threadIdx.x & 31;
    if (gw >= NN) return;
    int base = g_rowptr[gw];
    int end = g_rowptr[gw + 1];

    float4 acc = make_float4(-CUDART_INF_F, -CUDART_INF_F, -CUDART_INF_F, -CUDART_INF_F);
    int j = base;
    for (; j + 4 <= end; j += 4) {
        int s0 = g_csr[j + 0];
        int s1 = g_csr[j + 1];
        int s2 = g_csr[j + 2];
        int s3 = g_csr[j + 3];
        float4 v0 = ((const float4*)(xin + (size_t)s0 * D))[lane];
        float4 v1 = ((const float4*)(xin + (size_t)s1 * D))[lane];
        float4 v2 = ((const float4*)(xin + (size_t)s2 * D))[lane];
        float4 v3 = ((const float4*)(xin + (size_t)s3 * D))[lane];
        acc = f4max(acc, f4max(f4max(v0, v1), f4max(v2, v3)));
    }
    for (; j < end; j++) {
        int s0 = g_csr[j];
        float4 v0 = ((const float4*)(xin + (size_t)s0 * D))[lane];
        acc = f4max(acc, v0);
    }
    if (end == base) acc = make_float4(0.f, 0.f, 0.f, 0.f);
    ((float4*)(g_agg + (size_t)gw * D))[lane] = acc;
}

// ---------------- fused GEMM: out = relu(agg@W + bias + xin@R) ----------------
// M=NN, N=128, K=256 (two 128-halves: [agg|W] then [xin|R]).
// 128x128 block tile, 8x8 thread tile, f32x2 accumulators.
// Software-pipelined: next tile's global loads issued before this tile's math.
__global__ __launch_bounds__(256, 2)
void k_gemm(const float* __restrict__ Aagg, const float* __restrict__ Ax,
            const float* __restrict__ W, const float* __restrict__ R,
            const float* __restrict__ bias, float* __restrict__ out) {
    __shared__ __align__(16) float As[2][8][132];  // transposed A tile, padded
    __shared__ __align__(16) float Bs[2][8][128];

    const int tid = threadIdx.x;
    const int tx = tid & 15;        // 0..15 -> output col group (8 cols)
    const int ty = tid >> 4;        // 0..15 -> output row group (8 rows)
    const int m0 = blockIdx.x * 128;

    const int la_row = tid >> 1;          // 0..127
    const int la_col = (tid & 1) * 4;     // 0 or 4
    const int lb_row = tid >> 5;          // 0..7
    const int lb_col = (tid & 31) * 4;    // 0..124

    const int gm_load = m0 + la_row;
    const bool a_ok = (gm_load < NN);

    ull acc[8][4];
#pragma unroll
    for (int i = 0; i < 8; i++)
#pragma unroll
        for (int j = 0; j < 4; j++) acc[i][j] = 0ull;

    // prologue: load tile kb=0
    float4 av, bv;
    {
        av = make_float4(0.f, 0.f, 0.f, 0.f);
        if (a_ok) av = *(const float4*)(Aagg + (size_t)gm_load * D + la_col);
        bv = *(const float4*)(W + (size_t)lb_row * D + lb_col);
        As[0][la_col + 0][la_row] = av.x;
        As[0][la_col + 1][la_row] = av.y;
        As[0][la_col + 2][la_row] = av.z;
        As[0][la_col + 3][la_row] = av.w;
        *(float4*)&Bs[0][lb_row][lb_col] = bv;
    }
    __syncthreads();

#pragma unroll 1
    for (int kb = 0; kb < 32; kb++) {
        const int buf = kb & 1;
        const int nxt = 1 - buf;

        // issue next tile's global loads (no smem write yet)
        const int kn = kb + 1;
        if (kn < 32) {
            const float* A = (kn < 16) ? Aagg : Ax;
            const float* B = (kn < 16) ? W : R;
            const int k0 = (kn & 15) * 8;
            av = make_float4(0.f, 0.f, 0.f, 0.f);
            if (a_ok) av = *(const float4*)(A + (size_t)gm_load * D + k0 + la_col);
            bv = *(const float4*)(B + (size_t)(k0 + lb_row) * D + lb_col);
        }

        // math on current buffer
#pragma unroll
        for (int k = 0; k < 8; k++) {
            float4 a0 = *(const float4*)&As[buf][k][ty * 8];
            float4 a1 = *(const float4*)&As[buf][k][ty * 8 + 4];
            ull bp[4];
#pragma unroll
            for (int j = 0; j < 4; j++)
                bp[j] = ((const ull*)&Bs[buf][k][0])[tx * 4 + j];

            float a[8] = {a0.x, a0.y, a0.z, a0.w, a1.x, a1.y, a1.z, a1.w};
#pragma unroll
            for (int i = 0; i < 8; i++) {
                ull ap = pack2(a[i], a[i]);
#pragma unroll
                for (int j = 0; j < 4; j++) ffma2(acc[i][j], ap, bp[j]);
            }
        }

        // stage next tile into the other buffer
        if (kn < 32) {
            As[nxt][la_col + 0][la_row] = av.x;
            As[nxt][la_col + 1][la_row] = av.y;
            As[nxt][la_col + 2][la_row] = av.z;
            As[nxt][la_col + 3][la_row] = av.w;
            *(float4*)&Bs[nxt][lb_row][lb_col] = bv;
            __syncthreads();
        }
    }

    // epilogue: + bias, relu, store
    float4 bz0 = *(const float4*)&bias[tx * 8];
    float4 bz1 = *(const float4*)&bias[tx * 8 + 4];
    float bb[8] = {bz0.x, bz0.y, bz0.z, bz0.w, bz1.x, bz1.y, bz1.z, bz1.w};

#pragma unroll
    for (int i = 0; i < 8; i++) {
        int gm = m0 + ty * 8 + i;
        if (gm >= NN) continue;
        float o[8];
#pragma unroll
        for (int j = 0; j < 4; j++) {
            float2 v = unpack2(acc[i][j]);
            o[2 * j + 0] = fmaxf(v.x + bb[2 * j + 0], 0.f);
            o[2 * j + 1] = fmaxf(v.y + bb[2 * j + 1], 0.f);
        }
        float* op = out + (size_t)gm * D + tx * 8;
        *(float4*)(op + 0) = make_float4(o[0], o[1], o[2], o[3]);
        *(float4*)(op + 4) = make_float4(o[4], o[5], o[6], o[7]);
    }
}

// ---------------- launch ----------------
extern "C" void kernel_launch(void* const* d_in, const int* in_sizes, int n_in,
                              void* d_out, int out_size) {
    const float* x   = (const float*)d_in[0];
    const int*   ei  = (const int*)d_in[1];
    const float* W1  = (const float*)d_in[2];
    const float* b1  = (const float*)d_in[3];
    const float* R1  = (const float*)d_in[4];
    const float* W2  = (const float*)d_in[5];
    const float* b2  = (const float*)d_in[6];
    const float* R2  = (const float*)d_in[7];
    float* out = (float*)d_out;

    const int* src = ei;
    const int* dst = ei + NE;

    float* h;
    cudaGetSymbolAddress((void**)&h, g_h);
    float* agg;
    cudaGetSymbolAddress((void**)&agg, g_agg);

    // CSR build
    k_zero_deg<<<(NN + 255) / 256, 256>>>();
    k_count<<<(NE + 255) / 256, 256>>>(dst);
    k_scan<<<1, 1024>>>();
    k_fill<<<(NE + 255) / 256, 256>>>(src, dst);

    const int AGG_BLOCKS = (NN * 32 + 255) / 256;
    const int GEMM_BLOCKS = (NN + 127) / 128;

    // layer 1: x -> h
    k_agg<<<AGG_BLOCKS, 256>>>(x);
    k_gemm<<<GEMM_BLOCKS, 256>>>(agg, x, W1, R1, b1, h);
    // layer 2: h -> h
    k_agg<<<AGG_BLOCKS, 256>>>(h);
    k_gemm<<<GEMM_BLOCKS, 256>>>(agg, h, W2, R2, b2, h);
    // layer 3: h -> h
    k_agg<<<AGG_BLOCKS, 256>>>(h);
    k_gemm<<<GEMM_BLOCKS, 256>>>(agg, h, W2, R2, b2, h);
    // layer 4: h -> d_out
    k_agg<<<AGG_BLOCKS, 256>>>(h);
    k_gemm<<<GEMM_BLOCKS, 256>>>(agg, h, W2, R2, b2, out);
}

// round 15
// speedup vs baseline: 1.3790x; 1.3790x over previous
#include <cuda_runtime.h>
#include <cuda_bf16.h>
#include <math_constants.h>
#include <cstdint>

#define NN 50000
#define NE 600000
#define D 128

typedef unsigned long long ull;

// ---------------- device scratch (no allocs allowed) ----------------
__device__ int   g_deg[NN];
__device__ int   g_rowptr[NN + 1];
__device__ int   g_cursor[NN];
__device__ int   g_csr[NE];
__device__ float g_agg[(size_t)NN * D];
__device__ float g_h[(size_t)NN * D];

// ---------------- helpers ----------------
__device__ __forceinline__ uint32_t smem_u32(const void* p) {
    uint32_t a;
    asm("{ .reg .u64 t; cvta.to.shared.u64 t, %1; cvt.u32.u64 %0, t; }" : "=r"(a) : "l"(p));
    return a;
}

__device__ __forceinline__ void ldmat_x4(uint32_t& r0, uint32_t& r1, uint32_t& r2, uint32_t& r3,
                                         uint32_t addr) {
    asm volatile("ldmatrix.sync.aligned.m8n8.x4.shared.b16 {%0,%1,%2,%3}, [%4];"
                 : "=r"(r0), "=r"(r1), "=r"(r2), "=r"(r3) : "r"(addr));
}

__device__ __forceinline__ void mma_bf16(float* c, const uint32_t* a, const uint32_t* b) {
    asm volatile(
        "mma.sync.aligned.m16n8k16.row.col.f32.bf16.bf16.f32 "
        "{%0,%1,%2,%3}, {%4,%5,%6,%7}, {%8,%9}, {%0,%1,%2,%3};"
        : "+f"(c[0]), "+f"(c[1]), "+f"(c[2]), "+f"(c[3])
        : "r"(a[0]), "r"(a[1]), "r"(a[2]), "r"(a[3]), "r"(b[0]), "r"(b[1]));
}

// ---------------- CSR construction ----------------
__global__ void k_zero_deg() {
    int i = blockIdx.x * blockDim.x + threadIdx.x;
    if (i < NN) g_deg[i] = 0;
}

__global__ void k_count(const int* __restrict__ dst) {
    int e = blockIdx.x * blockDim.x + threadIdx.x;
    if (e < NE) atomicAdd(&g_deg[dst[e]], 1);
}

__global__ void k_scan() {
    __shared__ int sm[1024];
    const int t = threadIdx.x;
    const int C = (NN + 1023) / 1024;
    int start = t * C;
    int end = start + C; if (end > NN) end = NN;
    if (start > NN) start = NN;

    int s = 0;
    for (int i = start; i < end; i++) s += g_deg[i];
    sm[t] = s;
    __syncthreads();
    for (int off = 1; off < 1024; off <<= 1) {
        int v = 0;
        if (t >= off) v = sm[t - off];
        __syncthreads();
        if (t >= off) sm[t] += v;
        __syncthreads();
    }
    int run = sm[t] - s;
    for (int i = start; i < end; i++) {
        g_rowptr[i] = run;
        g_cursor[i] = run;
        run += g_deg[i];
    }
    if (t == 1023) g_rowptr[NN] = sm[1023];
}

__global__ void k_fill(const int* __restrict__ src, const int* __restrict__ dst) {
    int e = blockIdx.x * blockDim.x + threadIdx.x;
    if (e < NE) {
        int d = dst[e];
        int p = atomicAdd(&g_cursor[d], 1);
        g_csr[p] = src[e];
    }
}

// ---------------- aggregation: warp-per-node gather-max ----------------
__device__ __forceinline__ float4 f4max(float4 a, float4 b) {
    a.x = fmaxf(a.x, b.x); a.y = fmaxf(a.y, b.y);
    a.z = fmaxf(a.z, b.z); a.w = fmaxf(a.w, b.w);
    return a;
}

__global__ void k_agg(const float* __restrict__ xin) {
    int gw = (blockIdx.x * blockDim.x + threadIdx.x) >> 5;
    int lane = threadIdx.x & 31;
    if (gw >= NN) return;
    int base = g_rowptr[gw];
    int end = g_rowptr[gw + 1];

    float4 acc = make_float4(-CUDART_INF_F, -CUDART_INF_F, -CUDART_INF_F, -CUDART_INF_F);
    int j = base;
    for (; j + 4 <= end; j += 4) {
        int s0 = g_csr[j + 0];
        int s1 = g_csr[j + 1];
        int s2 = g_csr[j + 2];
        int s3 = g_csr[j + 3];
        float4 v0 = ((const float4*)(xin + (size_t)s0 * D))[lane];
        float4 v1 = ((const float4*)(xin + (size_t)s1 * D))[lane];
        float4 v2 = ((const float4*)(xin + (size_t)s2 * D))[lane];
        float4 v3 = ((const float4*)(xin + (size_t)s3 * D))[lane];
        acc = f4max(acc, f4max(f4max(v0, v1), f4max(v2, v3)));
    }
    for (; j < end; j++) {
        int s0 = g_csr[j];
        float4 v0 = ((const float4*)(xin + (size_t)s0 * D))[lane];
        acc = f4max(acc, v0);
    }
    if (end == base) acc = make_float4(0.f, 0.f, 0.f, 0.f);
    ((float4*)(g_agg + (size_t)gw * D))[lane] = acc;
}

// ---------------- tensor-core GEMM: out = relu(agg@W + bias + xin@R) ----------------
// 128x128 tile/CTA, 8 warps of 32x64. K=256 fp32 in 8 chunks of 32.
// Split precision: a = ah + al (bf16); 3 MMA passes: ah*bh + al*bh + ah*bl.
// SMEM: padded pitch 72 bf16 (144B) -> conflict-free ldmatrix, no swizzle.
// Layout per row: cols 0..31 = hi plane (k0..31), cols 32..63 = lo plane.
#define PITCH 72

__global__ __launch_bounds__(256, 2)
void k_gemm_mma(const float* __restrict__ Aagg, const float* __restrict__ Ax,
                const float* __restrict__ W, const float* __restrict__ R,
                const float* __restrict__ bias, float* __restrict__ out) {
    __shared__ __align__(16) __nv_bfloat16 sA[128 * PITCH];
    __shared__ __align__(16) __nv_bfloat16 sB[128 * PITCH];

    const int tid = threadIdx.x;
    const int wid = tid >> 5;
    const int lane = tid & 31;
    const int wm = wid & 3;       // warp row tile: rows wm*32..+32
    const int wn = wid >> 2;      // warp col tile: cols wn*64..+64
    const int m0 = blockIdx.x * 128;

    const uint32_t sa_u = smem_u32(sA);
    const uint32_t sb_u = smem_u32(sB);

    float acc[2][8][4];
#pragma unroll
    for (int i = 0; i < 2; i++)
#pragma unroll
        for (int j = 0; j < 8; j++)
#pragma unroll
            for (int k = 0; k < 4; k++) acc[i][j][k] = 0.f;

    // precomputed ldmatrix lane addresses (byte offsets from tile base)
    // A x4: row = lane&15, colgrp = (lane>>4)*8
    const uint32_t a_lane_off = (uint32_t)((lane & 15) * PITCH + ((lane >> 4) & 1) * 8) * 2;
    // B x4: n = (lane&7) + ((lane>>4)&1)*8, k = ((lane>>3)&1)*8
    const uint32_t b_lane_n = (lane & 7) + ((lane >> 4) & 1) * 8;
    const uint32_t b_lane_k = ((lane >> 3) & 1) * 8;

#pragma unroll 1
    for (int chunk = 0; chunk < 8; chunk++) {
        const float* Asrc = (chunk < 4) ? Aagg : Ax;
        const float* Bsrc = (chunk < 4) ? W : R;
        const int k0 = (chunk & 3) * 32;

        // ---- stage A: 128 rows x 16 float2 (coalesced) -> hi/lo planes ----
        for (int t = tid; t < 2048; t += 256) {
            int row = t >> 4, kp = t & 15;
            int gm = m0 + row;
            float2 v = make_float2(0.f, 0.f);
            if (gm < NN) v = *(const float2*)(Asrc + (size_t)gm * D + k0 + 2 * kp);
            __nv_bfloat16 h0 = __float2bfloat16_rn(v.x);
            __nv_bfloat16 h1 = __float2bfloat16_rn(v.y);
            __nv_bfloat16 l0 = __float2bfloat16_rn(v.x - __bfloat162float(h0));
            __nv_bfloat16 l1 = __float2bfloat16_rn(v.y - __bfloat162float(h1));
            uint32_t hp = ((uint32_t)__bfloat16_as_ushort(h1) << 16) | __bfloat16_as_ushort(h0);
            uint32_t lp = ((uint32_t)__bfloat16_as_ushort(l1) << 16) | __bfloat16_as_ushort(l0);
            *(uint32_t*)&sA[row * PITCH + 2 * kp]      = hp;
            *(uint32_t*)&sA[row * PITCH + 32 + 2 * kp] = lp;
        }
        // ---- stage B: transpose Bsrc[k][n] -> sB[n][k] (coalesced over n) ----
        for (int t = tid; t < 2048; t += 256) {
            int n = t & 127, kp = t >> 7;
            float v0 = Bsrc[(size_t)(k0 + 2 * kp) * D + n];
            float v1 = Bsrc[(size_t)(k0 + 2 * kp + 1) * D + n];
            __nv_bfloat16 h0 = __float2bfloat16_rn(v0);
            __nv_bfloat16 h1 = __float2bfloat16_rn(v1);
            __nv_bfloat16 l0 = __float2bfloat16_rn(v0 - __bfloat162float(h0));
            __nv_bfloat16 l1 = __float2bfloat16_rn(v1 - __bfloat162float(h1));
            uint32_t hp = ((uint32_t)__bfloat16_as_ushort(h1) << 16) | __bfloat16_as_ushort(h0);
            uint32_t lp = ((uint32_t)__bfloat16_as_ushort(l1) << 16) | __bfloat16_as_ushort(l0);
            *(uint32_t*)&sB[n * PITCH + 2 * kp]      = hp;
            *(uint32_t*)&sB[n * PITCH + 32 + 2 * kp] = lp;
        }
        __syncthreads();

        // ---- mma phase: 3 precision combos x 2 k16 steps ----
#pragma unroll
        for (int combo = 0; combo < 3; combo++) {
            const int aoff = (combo == 1) ? 32 : 0;  // lo plane of A for combo 1
            const int boff = (combo == 2) ? 32 : 0;  // lo plane of B for combo 2
#pragma unroll
            for (int s = 0; s < 2; s++) {
                const int kbase = s * 16;
                uint32_t a[2][4];
#pragma unroll
                for (int mt = 0; mt < 2; mt++) {
                    uint32_t addr = sa_u + (uint32_t)((wm * 32 + mt * 16) * PITCH + aoff + kbase) * 2
                                  + a_lane_off;
                    ldmat_x4(a[mt][0], a[mt][1], a[mt][2], a[mt][3], addr);
                }
#pragma unroll
                for (int np = 0; np < 4; np++) {   // n-pairs: 2 ntiles per ldmatrix.x4
                    uint32_t b[2][2];
                    uint32_t addr = sb_u
                        + (uint32_t)((wn * 64 + np * 16 + b_lane_n) * PITCH + boff + kbase + b_lane_k) * 2;
                    ldmat_x4(b[0][0], b[0][1], b[1][0], b[1][1], addr);
#pragma unroll
                    for (int mt = 0; mt < 2; mt++) {
                        mma_bf16(acc[mt][np * 2 + 0], a[mt], b[0]);
                        mma_bf16(acc[mt][np * 2 + 1], a[mt], b[1]);
                    }
                }
            }
        }
        __syncthreads();
    }

    // ---- epilogue: bias + relu + store ----
    const int g = lane >> 2, tg = lane & 3;
#pragma unroll
    for (int mt = 0; mt < 2; mt++) {
        int row0 = m0 + wm * 32 + mt * 16 + g;
        int row1 = row0 + 8;
#pragma unroll
        for (int nt = 0; nt < 8; nt++) {
            int col = wn * 64 + nt * 8 + tg * 2;
            float2 bz = *(const float2*)(bias + col);
            if (row0 < NN) {
                float2 o;
                o.x = fmaxf(acc[mt][nt][0] + bz.x, 0.f);
                o.y = fmaxf(acc[mt][nt][1] + bz.y, 0.f);
                *(float2*)(out + (size_t)row0 * D + col) = o;
            }
            if (row1 < NN) {
                float2 o;
                o.x = fmaxf(acc[mt][nt][2] + bz.x, 0.f);
                o.y = fmaxf(acc[mt][nt][3] + bz.y, 0.f);
                *(float2*)(out + (size_t)row1 * D + col) = o;
            }
        }
    }
}

// ---------------- launch ----------------
extern "C" void kernel_launch(void* const* d_in, const int* in_sizes, int n_in,
                              void* d_out, int out_size) {
    const float* x   = (const float*)d_in[0];
    const int*   ei  = (const int*)d_in[1];
    const float* W1  = (const float*)d_in[2];
    const float* b1  = (const float*)d_in[3];
    const float* R1  = (const float*)d_in[4];
    const float* W2  = (const float*)d_in[5];
    const float* b2  = (const float*)d_in[6];
    const float* R2  = (const float*)d_in[7];
    float* out = (float*)d_out;

    const int* src = ei;
    const int* dst = ei + NE;

    float* h;
    cudaGetSymbolAddress((void**)&h, g_h);
    float* agg;
    cudaGetSymbolAddress((void**)&agg, g_agg);

    // CSR build
    k_zero_deg<<<(NN + 255) / 256, 256>>>();
    k_count<<<(NE + 255) / 256, 256>>>(dst);
    k_scan<<<1, 1024>>>();
    k_fill<<<(NE + 255) / 256, 256>>>(src, dst);

    const int AGG_BLOCKS = (NN * 32 + 255) / 256;
    const int GEMM_BLOCKS = (NN + 127) / 128;  // 391

    // layer 1: x -> h
    k_agg<<<AGG_BLOCKS, 256>>>(x);
    k_gemm_mma<<<GEMM_BLOCKS, 256>>>(agg, x, W1, R1, b1, h);
    // layer 2: h -> h
    k_agg<<<AGG_BLOCKS, 256>>>(h);
    k_gemm_mma<<<GEMM_BLOCKS, 256>>>(agg, h, W2, R2, b2, h);
    // layer 3: h -> h
    k_agg<<<AGG_BLOCKS, 256>>>(h);
    k_gemm_mma<<<GEMM_BLOCKS, 256>>>(agg, h, W2, R2, b2, h);
    // layer 4: h -> d_out
    k_agg<<<AGG_BLOCKS, 256>>>(h);
    k_gemm_mma<<<GEMM_BLOCKS, 256>>>(agg, h, W2, R2, b2, out);
}